// round 15
// baseline (speedup 1.0000x reference)
#include <cuda_runtime.h>
#include <cuda_bf16.h>
#include <stdint.h>
#include <math.h>

// Problem constants (B=4,S=2048 -> T=8192 tokens)
#define TOK 8192
#define DD  1024
#define EE  8
#define FF  4096
#define RR  (TOK*2)

#define BM 128
#define BN 128
#define KC 32                 // bf16 k-elems per chunk (64B per row, packed)
#define NSTAGE 3
#define TILE_B (128*64)       // 8192 B per tile (packed, XOR-swizzled)
#define STAGE_B (4*TILE_B)    // Ah,Al,Bh,Bl = 32768 B
#define SMEM_GEMM (NSTAGE*STAGE_B)   // 98304 B -> 2 CTAs/SM

// ---------------- device scratch ------------------------------------------
__device__ __nv_bfloat16 g_Xh[(size_t)TOK*DD];
__device__ __nv_bfloat16 g_Xl[(size_t)TOK*DD];
__device__ __nv_bfloat16 g_W1h[(size_t)EE*FF*DD];   // [E][F][D] K-major
__device__ __nv_bfloat16 g_W1l[(size_t)EE*FF*DD];
__device__ __nv_bfloat16 g_W2h[(size_t)EE*DD*FF];   // [E][D][F] K-major
__device__ __nv_bfloat16 g_W2l[(size_t)EE*DD*FF];
__device__ __nv_bfloat16 g_Hh[(size_t)RR*FF];
__device__ __nv_bfloat16 g_Hl[(size_t)RR*FF];
__device__ int   g_count[EE];
__device__ int   g_cursor[EE];
__device__ int   g_rowStart[EE];
__device__ int   g_tokenOf[RR];
__device__ float g_wRow[RR];             // per expanded row combine weight
__device__ float g_w[RR];
__device__ int   g_tokExp[RR];

// ---------------- PTX helpers ----------------------------------------------
__device__ __forceinline__ uint32_t smem_u32(const void* p) {
    uint32_t a;
    asm("{ .reg .u64 t; cvta.to.shared.u64 t, %1; cvt.u32.u64 %0, t; }"
        : "=r"(a) : "l"(p));
    return a;
}
__device__ __forceinline__ void cp16(uint32_t dst, const void* src) {
    asm volatile("cp.async.cg.shared.global [%0], [%1], 16;"
                 :: "r"(dst), "l"(src) : "memory");
}
#define CP_COMMIT() asm volatile("cp.async.commit_group;" ::: "memory")
#define CP_WAIT2()  asm volatile("cp.async.wait_group 2;"  ::: "memory")

#define LDSM4(r, addr) \
    asm volatile("ldmatrix.sync.aligned.m8n8.x4.shared.b16 {%0,%1,%2,%3}, [%4];" \
        : "=r"((r)[0]), "=r"((r)[1]), "=r"((r)[2]), "=r"((r)[3]) : "r"(addr))

#define MMA_BF16(d, a, b) \
    asm volatile("mma.sync.aligned.m16n8k16.row.col.f32.bf16.bf16.f32 " \
        "{%0,%1,%2,%3}, {%4,%5,%6,%7}, {%8,%9}, {%0,%1,%2,%3};" \
        : "+f"((d)[0]), "+f"((d)[1]), "+f"((d)[2]), "+f"((d)[3]) \
        : "r"((a)[0]), "r"((a)[1]), "r"((a)[2]), "r"((a)[3]), \
          "r"((b)[0]), "r"((b)[1]))

// gelu(v) = 0.5 v (1 + tanh(z)) = v * sigmoid(2z)
__device__ __forceinline__ float gelu_tanh(float v) {
    float z2 = 1.5957691216057308f * (v + 0.044715f * v * v * v);
    return v / (1.0f + __expf(-z2));
}
__device__ __forceinline__ void split_bf16(float v, __nv_bfloat16& h, __nv_bfloat16& l) {
    h = __float2bfloat16(v);
    l = __float2bfloat16(v - __bfloat162float(h));
}

// ---------------- routing stages -------------------------------------------
__global__ void reset_kernel() {
    int i = threadIdx.x;
    if (i < EE) { g_count[i] = 0; g_cursor[i] = 0; }
}

// zero the output buffer (poisoned by harness each run)
__global__ void zero_out_kernel(float4* __restrict__ out) {
    int i = blockIdx.x * blockDim.x + threadIdx.x;
    if (i < TOK * (DD / 4)) out[i] = make_float4(0.f, 0.f, 0.f, 0.f);
}

// router + X hi/lo split fused; gate matrix staged transposed in smem
__global__ void router_kernel(const float* __restrict__ x,
                              const float* __restrict__ gw) {
    __shared__ float gwT[EE][DD];       // 32 KB, [e][d]
    int tid = threadIdx.x;
#pragma unroll
    for (int i = tid; i < DD * EE; i += 256) {
        int d = i >> 3, e = i & 7;
        gwT[e][d] = gw[i];
    }
    __syncthreads();

    int warp = (blockIdx.x * blockDim.x + tid) >> 5;
    if (warp >= TOK) return;
    int lane = tid & 31;
    const float4* xt = (const float4*)(x + (size_t)warp * DD);
    uint2* xh = (uint2*)(g_Xh + (size_t)warp * DD);
    uint2* xl = (uint2*)(g_Xl + (size_t)warp * DD);
    float acc[EE];
#pragma unroll
    for (int e = 0; e < EE; e++) acc[e] = 0.f;

#pragma unroll
    for (int k = 0; k < DD / 128; k++) {
        int i4 = k * 32 + lane;
        float4 v = xt[i4];
        __nv_bfloat16 h[4], l[4];
        split_bf16(v.x, h[0], l[0]); split_bf16(v.y, h[1], l[1]);
        split_bf16(v.z, h[2], l[2]); split_bf16(v.w, h[3], l[3]);
        xh[i4] = *(uint2*)h;
        xl[i4] = *(uint2*)l;
#pragma unroll
        for (int e = 0; e < EE; e++) {
            float4 g = ((const float4*)gwT[e])[i4];
            acc[e] = fmaf(v.x, g.x, acc[e]);
            acc[e] = fmaf(v.y, g.y, acc[e]);
            acc[e] = fmaf(v.z, g.z, acc[e]);
            acc[e] = fmaf(v.w, g.w, acc[e]);
        }
    }
#pragma unroll
    for (int e = 0; e < EE; e++)
#pragma unroll
        for (int off = 16; off > 0; off >>= 1)
            acc[e] += __shfl_xor_sync(0xffffffffu, acc[e], off);
    if (lane == 0) {
        int e0 = 0; float l0 = acc[0];
#pragma unroll
        for (int e = 1; e < EE; e++) if (acc[e] > l0) { l0 = acc[e]; e0 = e; }
        int e1 = -1; float l1 = -3.0e38f;
#pragma unroll
        for (int e = 0; e < EE; e++) if (e != e0 && acc[e] > l1) { l1 = acc[e]; e1 = e; }
        float p1 = expf(l1 - l0);
        float w0 = 1.0f / (1.0f + p1);
        float w1 = p1 / (1.0f + p1);
        g_tokExp[2 * warp]     = e0;
        g_tokExp[2 * warp + 1] = e1;
        g_w[2 * warp]     = w0;
        g_w[2 * warp + 1] = w1;
        atomicAdd(&g_count[e0], 1);
        atomicAdd(&g_count[e1], 1);
    }
}

__global__ void prefix_kernel() {
    int s = 0;
    for (int e = 0; e < EE; e++) { g_rowStart[e] = s; s += g_count[e]; }
}

__global__ void scatter_kernel() {
    int idx = blockIdx.x * blockDim.x + threadIdx.x;
    if (idx >= RR) return;
    int e   = g_tokExp[idx];
    int pos = atomicAdd(&g_cursor[e], 1);
    int row = g_rowStart[e] + pos;
    g_tokenOf[row] = idx >> 1;
    g_wRow[row]    = g_w[idx];
}

// transpose + split: in [E][Rr][Cc] fp32 -> out [E][Cc][Rr] bf16 hi/lo
template <int W>
__global__ void tsplit_kernel(const float* __restrict__ in) {
    constexpr int Rr = (W == 1) ? DD : FF;
    constexpr int Cc = (W == 1) ? FF : DD;
    __nv_bfloat16* outh = (W == 1) ? g_W1h : g_W2h;
    __nv_bfloat16* outl = (W == 1) ? g_W1l : g_W2l;
    __shared__ float t[32][33];
    int e = blockIdx.z;
    const float* ip = in + (size_t)e * Rr * Cc;
    __nv_bfloat16* oh = outh + (size_t)e * Rr * Cc;
    __nv_bfloat16* ol = outl + (size_t)e * Rr * Cc;
    int c0 = blockIdx.x * 32, r0 = blockIdx.y * 32;
    int tx = threadIdx.x, ty = threadIdx.y;
#pragma unroll
    for (int i = 0; i < 4; i++)
        t[ty + i * 8][tx] = ip[(size_t)(r0 + ty + i * 8) * Cc + c0 + tx];
    __syncthreads();
#pragma unroll
    for (int i = 0; i < 4; i++) {
        float v = t[tx][ty + i * 8];
        __nv_bfloat16 h, l; split_bf16(v, h, l);
        size_t o = (size_t)(c0 + ty + i * 8) * Rr + r0 + tx;
        oh[o] = h; ol[o] = l;
    }
}

// ---------------- grouped warp-MMA GEMM (R5 structure) -----------------------
// PHASE 1: H = gelu(gather(x) @ w1 + b1), K=DD, N=FF, out packed bf16 hi/lo
// PHASE 2: out[token] += w * (H @ w2 + b2)   (fused combine, atomic)
template <int PHASE>
__global__ __launch_bounds__(256, 2)
void moe_gemm(const float* __restrict__ bias, float* __restrict__ gout) {
    constexpr int K  = (PHASE == 1) ? DD : FF;
    constexpr int NT = (PHASE == 1) ? FF : DD;
    constexpr int NCHUNK = K / KC;

    extern __shared__ char smem[];
    const uint32_t su = smem_u32(smem);
    const int tid  = threadIdx.x;
    const int wid  = tid >> 5, lane = tid & 31;
    const int wm   = wid >> 2, wn = wid & 3;          // warp grid 2x4
    const int gid  = lane >> 2, tig = lane & 3;

    const int e   = blockIdx.z;
    const int cnt = g_count[e];
    const int m0  = blockIdx.y * BM;
    if (m0 >= cnt) return;
    const int n0   = blockIdx.x * BN;
    const int rs   = g_rowStart[e];
    const int mrem = min(cnt - m0, BM);

    const __nv_bfloat16 *Ah, *Al, *Bh, *Bl;
    if (PHASE == 1) {
        Ah = g_Xh; Al = g_Xl;
        Bh = g_W1h + (size_t)e * FF * DD; Bl = g_W1l + (size_t)e * FF * DD;
    } else {
        Ah = g_Hh; Al = g_Hl;
        Bh = g_W2h + (size_t)e * DD * FF; Bl = g_W2l + (size_t)e * DD * FF;
    }

    // ---- cp.async loader: 4 segs x 64 rows; 2 rows per thread per tile ----
    const int r0c  = tid >> 2;            // 0..63
    const int cseg = tid & 3;             // 16B segment within 64B row
    const uint32_t dsw = ((uint32_t)(cseg ^ ((r0c >> 1) & 3))) * 16u;
    const uint32_t d0  = (uint32_t)r0c * 64u + dsw;
    const uint32_t d1  = d0 + 64u * 64u;  // row +64: swizzle sel unchanged
    const int segE = cseg * 8;            // bf16 elem offset within chunk

    int ar0 = min(r0c,      mrem - 1);
    int ar1 = min(r0c + 64, mrem - 1);
    const int ga0 = (PHASE == 1) ? g_tokenOf[rs + m0 + ar0] : (rs + m0 + ar0);
    const int ga1 = (PHASE == 1) ? g_tokenOf[rs + m0 + ar1] : (rs + m0 + ar1);
    const __nv_bfloat16* pBh0 = Bh + (size_t)(n0 + r0c)      * K + segE;
    const __nv_bfloat16* pBh1 = Bh + (size_t)(n0 + r0c + 64) * K + segE;
    const __nv_bfloat16* pBl0 = Bl + (size_t)(n0 + r0c)      * K + segE;
    const __nv_bfloat16* pBl1 = Bl + (size_t)(n0 + r0c + 64) * K + segE;

    auto fill = [&](int buf, int c) {
        const size_t ko = (size_t)c * KC;
        const uint32_t b = su + buf * STAGE_B;
        const size_t a0 = (size_t)ga0 * K + segE + ko;
        const size_t a1 = (size_t)ga1 * K + segE + ko;
        cp16(b + d0,              Ah + a0);
        cp16(b + d1,              Ah + a1);
        cp16(b + TILE_B + d0,     Al + a0);
        cp16(b + TILE_B + d1,     Al + a1);
        cp16(b + 2*TILE_B + d0,   pBh0 + ko);
        cp16(b + 2*TILE_B + d1,   pBh1 + ko);
        cp16(b + 3*TILE_B + d0,   pBl0 + ko);
        cp16(b + 3*TILE_B + d1,   pBl1 + ko);
    };

    float acc[4][4][4];
#pragma unroll
    for (int i = 0; i < 4; i++)
#pragma unroll
        for (int j = 0; j < 4; j++)
#pragma unroll
            for (int q = 0; q < 4; q++) acc[i][j][q] = 0.f;

    // ldmatrix address bases (swizzle selector invariant under row+16/+64)
    const int aRow = wm * 64 + (lane & 15);
    const uint32_t aByte = (uint32_t)aRow * 64u;
    const uint32_t aS    = ((uint32_t)aRow >> 1) & 3u;
    const uint32_t aHi   = (uint32_t)(lane >> 4);          // k-half selector
    const int bRow = wn * 32 + (lane & 7) + ((lane >> 4) & 1) * 8;
    const uint32_t bByte = (uint32_t)bRow * 64u;
    const uint32_t bS    = ((uint32_t)bRow >> 1) & 3u;
    const uint32_t bHi   = (uint32_t)((lane >> 3) & 1);

    // ---- pipeline ----
    for (int s = 0; s < NSTAGE - 1; s++) { fill(s, s); CP_COMMIT(); }

    for (int c = 0; c < NCHUNK; c++) {
        int pre = c + NSTAGE - 1;
        if (pre < NCHUNK) fill(pre % NSTAGE, pre);
        CP_COMMIT();
        CP_WAIT2();
        __syncthreads();

        const uint32_t base = su + (c % NSTAGE) * STAGE_B;
#pragma unroll
        for (int ks = 0; ks < KC / 16; ks++) {
            const uint32_t segA = ((2u * ks + aHi) ^ aS) * 16u;
            const uint32_t segB = ((2u * ks + bHi) ^ bS) * 16u;
            uint32_t a[4][4], bh[4][2], bl[4][2];
#pragma unroll
            for (int mf = 0; mf < 4; mf++)
                LDSM4(a[mf], base + aByte + (uint32_t)mf * 1024u + segA);
#pragma unroll
            for (int pr = 0; pr < 2; pr++) {
                uint32_t bo = base + 2*TILE_B + bByte + (uint32_t)pr * 1024u + segB;
                uint32_t r[4];
                LDSM4(r, bo);
                bh[2*pr][0] = r[0]; bh[2*pr][1] = r[1];
                bh[2*pr+1][0] = r[2]; bh[2*pr+1][1] = r[3];
                LDSM4(r, bo + TILE_B);
                bl[2*pr][0] = r[0]; bl[2*pr][1] = r[1];
                bl[2*pr+1][0] = r[2]; bl[2*pr+1][1] = r[3];
            }
            // hh + hl terms with a = Ah
#pragma unroll
            for (int mf = 0; mf < 4; mf++)
#pragma unroll
                for (int nf = 0; nf < 4; nf++)
                    MMA_BF16(acc[mf][nf], a[mf], bh[nf]);
#pragma unroll
            for (int mf = 0; mf < 4; mf++)
#pragma unroll
                for (int nf = 0; nf < 4; nf++)
                    MMA_BF16(acc[mf][nf], a[mf], bl[nf]);
            // lh term: overwrite a with Al
#pragma unroll
            for (int mf = 0; mf < 4; mf++)
                LDSM4(a[mf], base + TILE_B + aByte + (uint32_t)mf * 1024u + segA);
#pragma unroll
            for (int mf = 0; mf < 4; mf++)
#pragma unroll
                for (int nf = 0; nf < 4; nf++)
                    MMA_BF16(acc[mf][nf], a[mf], bh[nf]);
        }
        __syncthreads();
    }

    // ---- epilogue ----
    const float* bp = bias + (size_t)e * NT;
#pragma unroll
    for (int mf = 0; mf < 4; mf++) {
#pragma unroll
        for (int half = 0; half < 2; half++) {
            int mrel = wm * 64 + mf * 16 + gid + half * 8;
            if (mrel >= mrem) continue;
            size_t grow = (size_t)(rs + m0 + mrel);
            int   tok = (PHASE == 2) ? g_tokenOf[grow] : 0;
            float wgt = (PHASE == 2) ? g_wRow[grow]    : 0.f;
#pragma unroll
            for (int nf = 0; nf < 4; nf++) {
                int nn = n0 + wn * 32 + nf * 8 + tig * 2;
                float v0 = acc[mf][nf][half * 2 + 0] + __ldg(bp + nn);
                float v1 = acc[mf][nf][half * 2 + 1] + __ldg(bp + nn + 1);
                if (PHASE == 1) {
                    float g0 = gelu_tanh(v0), g1 = gelu_tanh(v1);
                    __nv_bfloat16 h0, l0, h1, l1;
                    split_bf16(g0, h0, l0); split_bf16(g1, h1, l1);
                    uint32_t ph = (uint32_t)__bfloat16_as_ushort(h0)
                                | ((uint32_t)__bfloat16_as_ushort(h1) << 16);
                    uint32_t pl = (uint32_t)__bfloat16_as_ushort(l0)
                                | ((uint32_t)__bfloat16_as_ushort(l1) << 16);
                    *(uint32_t*)(g_Hh + grow * FF + nn) = ph;
                    *(uint32_t*)(g_Hl + grow * FF + nn) = pl;
                } else {
                    float* op = gout + (size_t)tok * DD + nn;
                    atomicAdd(op,     wgt * v0);
                    atomicAdd(op + 1, wgt * v1);
                }
            }
        }
    }
}

// ---------------- launch ------------------------------------------------------
extern "C" void kernel_launch(void* const* d_in, const int* in_sizes, int n_in,
                              void* d_out, int out_size) {
    const float* x  = (const float*)d_in[0];
    const float* gw = (const float*)d_in[1];
    const float* w1 = (const float*)d_in[2];
    const float* b1 = (const float*)d_in[3];
    const float* w2 = (const float*)d_in[4];
    const float* b2 = (const float*)d_in[5];
    float* out = (float*)d_out;

    // one-time host-side resources (no device memory involved)
    static cudaStream_t s2 = nullptr;
    static cudaEvent_t evFork = nullptr, evW1 = nullptr, evW2 = nullptr;
    if (s2 == nullptr) {
        cudaStreamCreateWithFlags(&s2, cudaStreamNonBlocking);
        cudaEventCreateWithFlags(&evFork, cudaEventDisableTiming);
        cudaEventCreateWithFlags(&evW1,   cudaEventDisableTiming);
        cudaEventCreateWithFlags(&evW2,   cudaEventDisableTiming);
    }

    cudaFuncSetAttribute(moe_gemm<1>, cudaFuncAttributeMaxDynamicSharedMemorySize, SMEM_GEMM);
    cudaFuncSetAttribute(moe_gemm<2>, cudaFuncAttributeMaxDynamicSharedMemorySize, SMEM_GEMM);

    // fork: weight conversions run on s2 in parallel with routing chain
    cudaEventRecord(evFork, 0);
    cudaStreamWaitEvent(s2, evFork, 0);
    tsplit_kernel<1><<<dim3(FF / 32, DD / 32, EE), dim3(32, 8), 0, s2>>>(w1);
    cudaEventRecord(evW1, s2);
    tsplit_kernel<2><<<dim3(DD / 32, FF / 32, EE), dim3(32, 8), 0, s2>>>(w2);
    cudaEventRecord(evW2, s2);

    // main chain
    reset_kernel<<<1, 32>>>();
    router_kernel<<<TOK / 8, 256>>>(x, gw);   // also writes g_Xh/g_Xl
    prefix_kernel<<<1, 1>>>();
    scatter_kernel<<<RR / 256, 256>>>();
    zero_out_kernel<<<(TOK * (DD / 4) + 255) / 256, 256>>>((float4*)out);

    cudaStreamWaitEvent(0, evW1, 0);          // W1 ready before gemm1
    moe_gemm<1><<<dim3(FF / 128, RR / 128, EE), 256, SMEM_GEMM>>>(b1, nullptr);
    cudaStreamWaitEvent(0, evW2, 0);          // W2 ready before gemm2
    moe_gemm<2><<<dim3(DD / 128, RR / 128, EE), 256, SMEM_GEMM>>>(b2, out);
}

// round 16
// speedup vs baseline: 1.4142x; 1.4142x over previous
#include <cuda_runtime.h>
#include <cuda_bf16.h>
#include <stdint.h>
#include <math.h>

// Problem constants (B=4,S=2048 -> T=8192 tokens)
#define TOK 8192
#define DD  1024
#define EE  8
#define FF  4096
#define RR  (TOK*2)

#define BM 128
#define BN 128
#define KC 32                 // fp32(tf32) k-elems per chunk (128B per row)
#define NSTAGE 3
#define TILE_B (128*128)      // 16384 B per tile (128 rows x 128B, swizzled)
#define STAGE_B (2*TILE_B)    // A,B = 32768 B
#define SMEM_GEMM (NSTAGE*STAGE_B)   // 98304 B -> 2 CTAs/SM

// ---------------- device scratch ------------------------------------------
__device__ float g_Xt[(size_t)TOK*DD];              // tf32-rounded x
__device__ float g_W1t[(size_t)EE*FF*DD];           // [E][F][D] K-major tf32
__device__ float g_W2t[(size_t)EE*DD*FF];           // [E][D][F] K-major tf32
__device__ float g_Ht[(size_t)RR*FF];               // tf32-rounded H
__device__ float g_Y[(size_t)RR*DD];
__device__ int   g_count[EE];
__device__ int   g_cursor[EE];
__device__ int   g_rowStart[EE];
__device__ int   g_tokenOf[RR];
__device__ int   g_rowIdx[RR];
__device__ float g_w[RR];
__device__ int   g_tokExp[RR];

// ---------------- PTX helpers ----------------------------------------------
__device__ __forceinline__ uint32_t smem_u32(const void* p) {
    uint32_t a;
    asm("{ .reg .u64 t; cvta.to.shared.u64 t, %1; cvt.u32.u64 %0, t; }"
        : "=r"(a) : "l"(p));
    return a;
}
__device__ __forceinline__ void cp16(uint32_t dst, const void* src) {
    asm volatile("cp.async.cg.shared.global [%0], [%1], 16;"
                 :: "r"(dst), "l"(src) : "memory");
}
#define CP_COMMIT() asm volatile("cp.async.commit_group;" ::: "memory")
#define CP_WAIT2()  asm volatile("cp.async.wait_group 2;"  ::: "memory")

#define LDSM4(r, addr) \
    asm volatile("ldmatrix.sync.aligned.m8n8.x4.shared.b16 {%0,%1,%2,%3}, [%4];" \
        : "=r"((r)[0]), "=r"((r)[1]), "=r"((r)[2]), "=r"((r)[3]) : "r"(addr))

#define MMA_TF32(d, a, b) \
    asm volatile("mma.sync.aligned.m16n8k8.row.col.f32.tf32.tf32.f32 " \
        "{%0,%1,%2,%3}, {%4,%5,%6,%7}, {%8,%9}, {%0,%1,%2,%3};" \
        : "+f"((d)[0]), "+f"((d)[1]), "+f"((d)[2]), "+f"((d)[3]) \
        : "r"((a)[0]), "r"((a)[1]), "r"((a)[2]), "r"((a)[3]), \
          "r"((b)[0]), "r"((b)[1]))

__device__ __forceinline__ float to_tf32(float v) {
    float r;
    asm("cvt.rna.tf32.f32 %0, %1;" : "=f"(r) : "f"(v));
    return r;
}

// gelu(v) = 0.5 v (1 + tanh(z)) = v * sigmoid(2z)
__device__ __forceinline__ float gelu_tanh(float v) {
    float z2 = 1.5957691216057308f * (v + 0.044715f * v * v * v);
    return v / (1.0f + __expf(-z2));
}

// ---------------- routing stages -------------------------------------------
__global__ void reset_kernel() {
    int i = threadIdx.x;
    if (i < EE) { g_count[i] = 0; g_cursor[i] = 0; }
}

// router + X tf32 rounding fused; gate matrix staged transposed in smem
__global__ void router_kernel(const float* __restrict__ x,
                              const float* __restrict__ gw) {
    __shared__ float gwT[EE][DD];       // 32 KB, [e][d]
    int tid = threadIdx.x;
#pragma unroll
    for (int i = tid; i < DD * EE; i += 256) {
        int d = i >> 3, e = i & 7;
        gwT[e][d] = gw[i];
    }
    __syncthreads();

    int warp = (blockIdx.x * blockDim.x + tid) >> 5;
    if (warp >= TOK) return;
    int lane = tid & 31;
    const float4* xt = (const float4*)(x + (size_t)warp * DD);
    float4* xo = (float4*)(g_Xt + (size_t)warp * DD);
    float acc[EE];
#pragma unroll
    for (int e = 0; e < EE; e++) acc[e] = 0.f;

#pragma unroll
    for (int k = 0; k < DD / 128; k++) {
        int i4 = k * 32 + lane;
        float4 v = xt[i4];
        float4 t;
        t.x = to_tf32(v.x); t.y = to_tf32(v.y);
        t.z = to_tf32(v.z); t.w = to_tf32(v.w);
        xo[i4] = t;
#pragma unroll
        for (int e = 0; e < EE; e++) {
            float4 g = ((const float4*)gwT[e])[i4];
            acc[e] = fmaf(v.x, g.x, acc[e]);
            acc[e] = fmaf(v.y, g.y, acc[e]);
            acc[e] = fmaf(v.z, g.z, acc[e]);
            acc[e] = fmaf(v.w, g.w, acc[e]);
        }
    }
#pragma unroll
    for (int e = 0; e < EE; e++)
#pragma unroll
        for (int off = 16; off > 0; off >>= 1)
            acc[e] += __shfl_xor_sync(0xffffffffu, acc[e], off);
    if (lane == 0) {
        int e0 = 0; float l0 = acc[0];
#pragma unroll
        for (int e = 1; e < EE; e++) if (acc[e] > l0) { l0 = acc[e]; e0 = e; }
        int e1 = -1; float l1 = -3.0e38f;
#pragma unroll
        for (int e = 0; e < EE; e++) if (e != e0 && acc[e] > l1) { l1 = acc[e]; e1 = e; }
        float p1 = expf(l1 - l0);
        float w0 = 1.0f / (1.0f + p1);
        float w1 = p1 / (1.0f + p1);
        g_tokExp[2 * warp]     = e0;
        g_tokExp[2 * warp + 1] = e1;
        g_w[2 * warp]     = w0;
        g_w[2 * warp + 1] = w1;
        atomicAdd(&g_count[e0], 1);
        atomicAdd(&g_count[e1], 1);
    }
}

__global__ void prefix_kernel() {
    int s = 0;
    for (int e = 0; e < EE; e++) { g_rowStart[e] = s; s += g_count[e]; }
}

__global__ void scatter_kernel() {
    int idx = blockIdx.x * blockDim.x + threadIdx.x;
    if (idx >= RR) return;
    int e   = g_tokExp[idx];
    int pos = atomicAdd(&g_cursor[e], 1);
    int row = g_rowStart[e] + pos;
    g_tokenOf[row] = idx >> 1;
    g_rowIdx[idx]  = row;
}

// transpose + tf32 round: in [E][Rr][Cc] fp32 -> out [E][Cc][Rr]
template <int W>
__global__ void wtrans_kernel(const float* __restrict__ in) {
    constexpr int Rr = (W == 1) ? DD : FF;
    constexpr int Cc = (W == 1) ? FF : DD;
    float* outp = (W == 1) ? g_W1t : g_W2t;
    __shared__ float t[32][33];
    int e = blockIdx.z;
    const float* ip = in + (size_t)e * Rr * Cc;
    float* op = outp + (size_t)e * Rr * Cc;
    int c0 = blockIdx.x * 32, r0 = blockIdx.y * 32;
    int tx = threadIdx.x, ty = threadIdx.y;
#pragma unroll
    for (int i = 0; i < 4; i++)
        t[ty + i * 8][tx] = ip[(size_t)(r0 + ty + i * 8) * Cc + c0 + tx];
    __syncthreads();
#pragma unroll
    for (int i = 0; i < 4; i++)
        op[(size_t)(c0 + ty + i * 8) * Rr + r0 + tx] = to_tf32(t[tx][ty + i * 8]);
}

// ---------------- grouped 1xTF32 warp-MMA GEMM -------------------------------
// PHASE 1: H = gelu(gather(x) @ w1 + b1), K=DD, N=FF, out tf32-rounded fp32
// PHASE 2: Y = H @ w2 + b2,               K=FF, N=DD, out fp32
template <int PHASE>
__global__ __launch_bounds__(256, 2)
void moe_gemm(const float* __restrict__ bias) {
    constexpr int K  = (PHASE == 1) ? DD : FF;
    constexpr int NT = (PHASE == 1) ? FF : DD;
    constexpr int NCHUNK = K / KC;

    extern __shared__ char smem[];
    const uint32_t su = smem_u32(smem);
    const int tid  = threadIdx.x;
    const int wid  = tid >> 5, lane = tid & 31;
    const int wm   = wid >> 2, wn = wid & 3;          // warp grid 2x4
    const int gid  = lane >> 2, tig = lane & 3;

    const int e   = blockIdx.z;
    const int cnt = g_count[e];
    const int m0  = blockIdx.y * BM;
    if (m0 >= cnt) return;
    const int n0   = blockIdx.x * BN;
    const int rs   = g_rowStart[e];
    const int mrem = min(cnt - m0, BM);

    const float *A, *B;
    if (PHASE == 1) {
        A = g_Xt;
        B = g_W1t + (size_t)e * FF * DD;
    } else {
        A = g_Ht;
        B = g_W2t + (size_t)e * DD * FF;
    }

    // ---- cp.async loader: 128 rows x 8 segs of 16B; 4 (row,seg) per thread
    const int seg  = tid & 7;             // 16B segment (constant across it)
    const int rB   = tid >> 3;            // base row 0..31
    const uint32_t swb = ((uint32_t)(seg ^ (rB & 7))) * 16u;   // (rB&7) invariant +32
    uint32_t dA[4];
    int      ga[4];
    const float* pB[4];
#pragma unroll
    for (int it = 0; it < 4; it++) {
        int r = rB + it * 32;
        dA[it] = (uint32_t)r * 128u + swb;
        int ar = min(r, mrem - 1);
        ga[it] = (PHASE == 1) ? g_tokenOf[rs + m0 + ar] : (rs + m0 + ar);
        pB[it] = B + (size_t)(n0 + r) * K + seg * 4;
    }

    auto fill = [&](int buf, int c) {
        const size_t ko = (size_t)c * KC;
        const uint32_t b = su + buf * STAGE_B;
#pragma unroll
        for (int it = 0; it < 4; it++) {
            cp16(b + dA[it],          A + (size_t)ga[it] * K + seg * 4 + ko);
            cp16(b + TILE_B + dA[it], pB[it] + ko);
        }
    };

    float acc[4][4][4];
#pragma unroll
    for (int i = 0; i < 4; i++)
#pragma unroll
        for (int j = 0; j < 4; j++)
#pragma unroll
            for (int q = 0; q < 4; q++) acc[i][j][q] = 0.f;

    // ldmatrix bases
    const int aRowL = (lane & 7) + ((lane >> 3) & 1) * 8;   // row within m16
    const uint32_t aRswz = (uint32_t)(lane & 7);            // (row & 7)
    const uint32_t aHi   = (uint32_t)(lane >> 4);
    const uint32_t aBase = (uint32_t)(wm * 64 + aRowL) * 128u;
    const int bRowL = (lane & 7) + ((lane >> 4) & 1) * 8;
    const uint32_t bRswz = (uint32_t)(lane & 7);
    const uint32_t bHi   = (uint32_t)((lane >> 3) & 1);
    const uint32_t bBase = (uint32_t)(wn * 32 + bRowL) * 128u;

    // ---- pipeline ----
    for (int s = 0; s < NSTAGE - 1; s++) { fill(s, s); CP_COMMIT(); }

    for (int c = 0; c < NCHUNK; c++) {
        int pre = c + NSTAGE - 1;
        if (pre < NCHUNK) fill(pre % NSTAGE, pre);
        CP_COMMIT();
        CP_WAIT2();
        __syncthreads();

        const uint32_t base = su + (c % NSTAGE) * STAGE_B;
#pragma unroll
        for (int ks = 0; ks < KC / 8; ks++) {             // 4 k8 steps
            const uint32_t segA = ((2u * ks + aHi) ^ aRswz) * 16u;
            const uint32_t segB = ((2u * ks + bHi) ^ bRswz) * 16u;
            uint32_t a[4][4], bf[4][2];
#pragma unroll
            for (int mf = 0; mf < 4; mf++)
                LDSM4(a[mf], base + aBase + (uint32_t)mf * 2048u + segA);
#pragma unroll
            for (int pr = 0; pr < 2; pr++) {
                uint32_t r[4];
                LDSM4(r, base + TILE_B + bBase + (uint32_t)pr * 2048u + segB);
                bf[2*pr][0]   = r[0]; bf[2*pr][1]   = r[1];
                bf[2*pr+1][0] = r[2]; bf[2*pr+1][1] = r[3];
            }
#pragma unroll
            for (int mf = 0; mf < 4; mf++)
#pragma unroll
                for (int nf = 0; nf < 4; nf++)
                    MMA_TF32(acc[mf][nf], a[mf], bf[nf]);
        }
        __syncthreads();
    }

    // ---- epilogue: bias + GELU (+tf32 round) straight from registers ----
    const float* bp = bias + (size_t)e * NT;
#pragma unroll
    for (int mf = 0; mf < 4; mf++) {
#pragma unroll
        for (int nf = 0; nf < 4; nf++) {
            int nn = n0 + wn * 32 + nf * 8 + tig * 2;
            float b0v = __ldg(bp + nn), b1v = __ldg(bp + nn + 1);
#pragma unroll
            for (int half = 0; half < 2; half++) {
                int mrel = wm * 64 + mf * 16 + gid + half * 8;
                if (mrel >= mrem) continue;
                size_t grow = (size_t)(rs + m0 + mrel);
                float v0 = acc[mf][nf][half * 2 + 0] + b0v;
                float v1 = acc[mf][nf][half * 2 + 1] + b1v;
                float2 o;
                if (PHASE == 1) {
                    o.x = to_tf32(gelu_tanh(v0));
                    o.y = to_tf32(gelu_tanh(v1));
                    *(float2*)(g_Ht + grow * FF + nn) = o;
                } else {
                    o.x = v0; o.y = v1;
                    *(float2*)(g_Y + grow * DD + nn) = o;
                }
            }
        }
    }
}

// ---------------- combine ----------------------------------------------------
__global__ void combine_kernel(float* __restrict__ out) {
    int idx = blockIdx.x * blockDim.x + threadIdx.x;
    if (idx >= TOK * (DD / 4)) return;
    int t  = idx / (DD / 4);
    int n4 = idx % (DD / 4);
    int   r0 = g_rowIdx[2 * t],     r1 = g_rowIdx[2 * t + 1];
    float w0 = g_w[2 * t],          w1 = g_w[2 * t + 1];
    float4 y0 = ((const float4*)(g_Y + (size_t)r0 * DD))[n4];
    float4 y1 = ((const float4*)(g_Y + (size_t)r1 * DD))[n4];
    float4 o;
    o.x = w0 * y0.x + w1 * y1.x;
    o.y = w0 * y0.y + w1 * y1.y;
    o.z = w0 * y0.z + w1 * y1.z;
    o.w = w0 * y0.w + w1 * y1.w;
    ((float4*)out)[idx] = o;
}

// ---------------- launch ------------------------------------------------------
extern "C" void kernel_launch(void* const* d_in, const int* in_sizes, int n_in,
                              void* d_out, int out_size) {
    const float* x  = (const float*)d_in[0];
    const float* gw = (const float*)d_in[1];
    const float* w1 = (const float*)d_in[2];
    const float* b1 = (const float*)d_in[3];
    const float* w2 = (const float*)d_in[4];
    const float* b2 = (const float*)d_in[5];
    float* out = (float*)d_out;

    // one-time host-side resources (no device memory involved)
    static cudaStream_t s2 = nullptr;
    static cudaEvent_t evFork = nullptr, evW1 = nullptr, evW2 = nullptr;
    if (s2 == nullptr) {
        cudaStreamCreateWithFlags(&s2, cudaStreamNonBlocking);
        cudaEventCreateWithFlags(&evFork, cudaEventDisableTiming);
        cudaEventCreateWithFlags(&evW1,   cudaEventDisableTiming);
        cudaEventCreateWithFlags(&evW2,   cudaEventDisableTiming);
    }

    cudaFuncSetAttribute(moe_gemm<1>, cudaFuncAttributeMaxDynamicSharedMemorySize, SMEM_GEMM);
    cudaFuncSetAttribute(moe_gemm<2>, cudaFuncAttributeMaxDynamicSharedMemorySize, SMEM_GEMM);

    // fork: weight conversions run on s2 in parallel with routing chain
    cudaEventRecord(evFork, 0);
    cudaStreamWaitEvent(s2, evFork, 0);
    wtrans_kernel<1><<<dim3(FF / 32, DD / 32, EE), dim3(32, 8), 0, s2>>>(w1);
    cudaEventRecord(evW1, s2);
    wtrans_kernel<2><<<dim3(DD / 32, FF / 32, EE), dim3(32, 8), 0, s2>>>(w2);
    cudaEventRecord(evW2, s2);

    // main chain
    reset_kernel<<<1, 32>>>();
    router_kernel<<<TOK / 8, 256>>>(x, gw);   // also writes g_Xt
    prefix_kernel<<<1, 1>>>();
    scatter_kernel<<<RR / 256, 256>>>();

    cudaStreamWaitEvent(0, evW1, 0);          // W1 ready before gemm1
    moe_gemm<1><<<dim3(FF / 128, RR / 128, EE), 256, SMEM_GEMM>>>(b1);
    cudaStreamWaitEvent(0, evW2, 0);          // W2 ready before gemm2
    moe_gemm<2><<<dim3(DD / 128, RR / 128, EE), 256, SMEM_GEMM>>>(b2);

    combine_kernel<<<(TOK * (DD / 4) + 255) / 256, 256>>>(out);
}

// round 17
// speedup vs baseline: 2.2060x; 1.5598x over previous
#include <cuda_runtime.h>
#include <cuda_fp16.h>
#include <stdint.h>
#include <math.h>

// Problem constants (B=4,S=2048 -> T=8192 tokens)
#define TOK 8192
#define DD  1024
#define EE  8
#define FF  4096
#define RR  (TOK*2)

#define BM 128
#define BN 128
#define KC 32                 // fp16 k-elems per chunk (64B per row, packed)
#define NSTAGE 3
#define TILE_B (128*64)       // 8192 B per tile
#define STAGE_B (2*TILE_B)    // A,B = 16384 B
#define SMEM_GEMM (NSTAGE*STAGE_B)   // 49152 B -> 2 CTAs/SM

// ---------------- device scratch ------------------------------------------
__device__ __half g_Xh[(size_t)TOK*DD];
__device__ __half g_W1h[(size_t)EE*FF*DD];   // [E][F][D] K-major
__device__ __half g_W2h[(size_t)EE*DD*FF];   // [E][D][F] K-major
__device__ __half g_Hh[(size_t)RR*FF];
__device__ float g_Y[(size_t)RR*DD];
__device__ int   g_count[EE];
__device__ int   g_cursor[EE];
__device__ int   g_rowStart[EE];
__device__ int   g_tokenOf[RR];
__device__ int   g_rowIdx[RR];
__device__ float g_w[RR];
__device__ int   g_tokExp[RR];

// ---------------- PTX helpers ----------------------------------------------
__device__ __forceinline__ uint32_t smem_u32(const void* p) {
    uint32_t a;
    asm("{ .reg .u64 t; cvta.to.shared.u64 t, %1; cvt.u32.u64 %0, t; }"
        : "=r"(a) : "l"(p));
    return a;
}
__device__ __forceinline__ void cp16(uint32_t dst, const void* src) {
    asm volatile("cp.async.cg.shared.global [%0], [%1], 16;"
                 :: "r"(dst), "l"(src) : "memory");
}
#define CP_COMMIT() asm volatile("cp.async.commit_group;" ::: "memory")
#define CP_WAIT2()  asm volatile("cp.async.wait_group 2;"  ::: "memory")

#define LDSM4(r, addr) \
    asm volatile("ldmatrix.sync.aligned.m8n8.x4.shared.b16 {%0,%1,%2,%3}, [%4];" \
        : "=r"((r)[0]), "=r"((r)[1]), "=r"((r)[2]), "=r"((r)[3]) : "r"(addr))

#define MMA_F16(d, a, b) \
    asm volatile("mma.sync.aligned.m16n8k16.row.col.f32.f16.f16.f32 " \
        "{%0,%1,%2,%3}, {%4,%5,%6,%7}, {%8,%9}, {%0,%1,%2,%3};" \
        : "+f"((d)[0]), "+f"((d)[1]), "+f"((d)[2]), "+f"((d)[3]) \
        : "r"((a)[0]), "r"((a)[1]), "r"((a)[2]), "r"((a)[3]), \
          "r"((b)[0]), "r"((b)[1]))

// gelu(v) = 0.5 v (1 + tanh(z)) = v * sigmoid(2z)
__device__ __forceinline__ float gelu_tanh(float v) {
    float z2 = 1.5957691216057308f * (v + 0.044715f * v * v * v);
    return v / (1.0f + __expf(-z2));
}

// ---------------- routing stages -------------------------------------------
__global__ void reset_kernel() {
    int i = threadIdx.x;
    if (i < EE) { g_count[i] = 0; g_cursor[i] = 0; }
}

// router + X fp16 conversion fused; gate matrix staged transposed in smem
__global__ void router_kernel(const float* __restrict__ x,
                              const float* __restrict__ gw) {
    __shared__ float gwT[EE][DD];       // 32 KB, [e][d]
    int tid = threadIdx.x;
#pragma unroll
    for (int i = tid; i < DD * EE; i += 256) {
        int d = i >> 3, e = i & 7;
        gwT[e][d] = gw[i];
    }
    __syncthreads();

    int warp = (blockIdx.x * blockDim.x + tid) >> 5;
    if (warp >= TOK) return;
    int lane = tid & 31;
    const float4* xt = (const float4*)(x + (size_t)warp * DD);
    uint2* xo = (uint2*)(g_Xh + (size_t)warp * DD);
    float acc[EE];
#pragma unroll
    for (int e = 0; e < EE; e++) acc[e] = 0.f;

#pragma unroll
    for (int k = 0; k < DD / 128; k++) {
        int i4 = k * 32 + lane;
        float4 v = xt[i4];
        __half h[4];
        h[0] = __float2half_rn(v.x); h[1] = __float2half_rn(v.y);
        h[2] = __float2half_rn(v.z); h[3] = __float2half_rn(v.w);
        xo[i4] = *(uint2*)h;
#pragma unroll
        for (int e = 0; e < EE; e++) {
            float4 g = ((const float4*)gwT[e])[i4];
            acc[e] = fmaf(v.x, g.x, acc[e]);
            acc[e] = fmaf(v.y, g.y, acc[e]);
            acc[e] = fmaf(v.z, g.z, acc[e]);
            acc[e] = fmaf(v.w, g.w, acc[e]);
        }
    }
#pragma unroll
    for (int e = 0; e < EE; e++)
#pragma unroll
        for (int off = 16; off > 0; off >>= 1)
            acc[e] += __shfl_xor_sync(0xffffffffu, acc[e], off);
    if (lane == 0) {
        int e0 = 0; float l0 = acc[0];
#pragma unroll
        for (int e = 1; e < EE; e++) if (acc[e] > l0) { l0 = acc[e]; e0 = e; }
        int e1 = -1; float l1 = -3.0e38f;
#pragma unroll
        for (int e = 0; e < EE; e++) if (e != e0 && acc[e] > l1) { l1 = acc[e]; e1 = e; }
        float p1 = expf(l1 - l0);
        float w0 = 1.0f / (1.0f + p1);
        float w1 = p1 / (1.0f + p1);
        g_tokExp[2 * warp]     = e0;
        g_tokExp[2 * warp + 1] = e1;
        g_w[2 * warp]     = w0;
        g_w[2 * warp + 1] = w1;
        atomicAdd(&g_count[e0], 1);
        atomicAdd(&g_count[e1], 1);
    }
}

__global__ void prefix_kernel() {
    int s = 0;
    for (int e = 0; e < EE; e++) { g_rowStart[e] = s; s += g_count[e]; }
}

__global__ void scatter_kernel() {
    int idx = blockIdx.x * blockDim.x + threadIdx.x;
    if (idx >= RR) return;
    int e   = g_tokExp[idx];
    int pos = atomicAdd(&g_cursor[e], 1);
    int row = g_rowStart[e] + pos;
    g_tokenOf[row] = idx >> 1;
    g_rowIdx[idx]  = row;
}

// transpose + fp16 convert: in [E][Rr][Cc] fp32 -> out [E][Cc][Rr] half
template <int W>
__global__ void wtrans_kernel(const float* __restrict__ in) {
    constexpr int Rr = (W == 1) ? DD : FF;
    constexpr int Cc = (W == 1) ? FF : DD;
    __half* outp = (W == 1) ? g_W1h : g_W2h;
    __shared__ float t[32][33];
    int e = blockIdx.z;
    const float* ip = in + (size_t)e * Rr * Cc;
    __half* op = outp + (size_t)e * Rr * Cc;
    int c0 = blockIdx.x * 32, r0 = blockIdx.y * 32;
    int tx = threadIdx.x, ty = threadIdx.y;
#pragma unroll
    for (int i = 0; i < 4; i++)
        t[ty + i * 8][tx] = ip[(size_t)(r0 + ty + i * 8) * Cc + c0 + tx];
    __syncthreads();
#pragma unroll
    for (int i = 0; i < 4; i++)
        op[(size_t)(c0 + ty + i * 8) * Rr + r0 + tx] =
            __float2half_rn(t[tx][ty + i * 8]);
}

// ---------------- grouped single-pass FP16 warp-MMA GEMM ---------------------
// PHASE 1: H = gelu(gather(x) @ w1 + b1), K=DD, N=FF, out fp16
// PHASE 2: Y = H @ w2 + b2,               K=FF, N=DD, out fp32
template <int PHASE>
__global__ __launch_bounds__(256, 2)
void moe_gemm(const float* __restrict__ bias) {
    constexpr int K  = (PHASE == 1) ? DD : FF;
    constexpr int NT = (PHASE == 1) ? FF : DD;
    constexpr int NCHUNK = K / KC;

    extern __shared__ char smem[];
    const uint32_t su = smem_u32(smem);
    const int tid  = threadIdx.x;
    const int wid  = tid >> 5, lane = tid & 31;
    const int wm   = wid >> 2, wn = wid & 3;          // warp grid 2x4
    const int gid  = lane >> 2, tig = lane & 3;

    const int e   = blockIdx.z;
    const int cnt = g_count[e];
    const int m0  = blockIdx.y * BM;
    if (m0 >= cnt) return;
    const int n0   = blockIdx.x * BN;
    const int rs   = g_rowStart[e];
    const int mrem = min(cnt - m0, BM);

    const __half *A, *B;
    if (PHASE == 1) {
        A = g_Xh;
        B = g_W1h + (size_t)e * FF * DD;
    } else {
        A = g_Hh;
        B = g_W2h + (size_t)e * DD * FF;
    }

    // ---- cp.async loader: 4 segs x 64 rows; 2 rows per thread per tile ----
    const int r0c  = tid >> 2;            // 0..63
    const int cseg = tid & 3;             // 16B segment within 64B row
    const uint32_t dsw = ((uint32_t)(cseg ^ ((r0c >> 1) & 3))) * 16u;
    const uint32_t d0  = (uint32_t)r0c * 64u + dsw;
    const uint32_t d1  = d0 + 64u * 64u;  // row +64: swizzle sel unchanged
    const int segE = cseg * 8;            // fp16 elem offset within chunk

    int ar0 = min(r0c,      mrem - 1);
    int ar1 = min(r0c + 64, mrem - 1);
    const int ga0 = (PHASE == 1) ? g_tokenOf[rs + m0 + ar0] : (rs + m0 + ar0);
    const int ga1 = (PHASE == 1) ? g_tokenOf[rs + m0 + ar1] : (rs + m0 + ar1);
    const __half* pB0 = B + (size_t)(n0 + r0c)      * K + segE;
    const __half* pB1 = B + (size_t)(n0 + r0c + 64) * K + segE;

    auto fill = [&](int buf, int c) {
        const size_t ko = (size_t)c * KC;
        const uint32_t b = su + buf * STAGE_B;
        cp16(b + d0,            A + (size_t)ga0 * K + segE + ko);
        cp16(b + d1,            A + (size_t)ga1 * K + segE + ko);
        cp16(b + TILE_B + d0,   pB0 + ko);
        cp16(b + TILE_B + d1,   pB1 + ko);
    };

    float acc[4][4][4];
#pragma unroll
    for (int i = 0; i < 4; i++)
#pragma unroll
        for (int j = 0; j < 4; j++)
#pragma unroll
            for (int q = 0; q < 4; q++) acc[i][j][q] = 0.f;

    // ldmatrix address bases (swizzle selector invariant under row+16/+64)
    const int aRow = wm * 64 + (lane & 15);
    const uint32_t aByte = (uint32_t)aRow * 64u;
    const uint32_t aS    = ((uint32_t)aRow >> 1) & 3u;
    const uint32_t aHi   = (uint32_t)(lane >> 4);          // k-half selector
    const int bRow = wn * 32 + (lane & 7) + ((lane >> 4) & 1) * 8;
    const uint32_t bByte = (uint32_t)bRow * 64u;
    const uint32_t bS    = ((uint32_t)bRow >> 1) & 3u;
    const uint32_t bHi   = (uint32_t)((lane >> 3) & 1);

    // ---- pipeline ----
    for (int s = 0; s < NSTAGE - 1; s++) { fill(s, s); CP_COMMIT(); }

    for (int c = 0; c < NCHUNK; c++) {
        int pre = c + NSTAGE - 1;
        if (pre < NCHUNK) fill(pre % NSTAGE, pre);
        CP_COMMIT();
        CP_WAIT2();
        __syncthreads();

        const uint32_t base = su + (c % NSTAGE) * STAGE_B;
#pragma unroll
        for (int ks = 0; ks < KC / 16; ks++) {
            const uint32_t segA = ((2u * ks + aHi) ^ aS) * 16u;
            const uint32_t segB = ((2u * ks + bHi) ^ bS) * 16u;
            uint32_t a[4][4], bf[4][2];
#pragma unroll
            for (int mf = 0; mf < 4; mf++)
                LDSM4(a[mf], base + aByte + (uint32_t)mf * 1024u + segA);
#pragma unroll
            for (int pr = 0; pr < 2; pr++) {
                uint32_t r[4];
                LDSM4(r, base + TILE_B + bByte + (uint32_t)pr * 1024u + segB);
                bf[2*pr][0]   = r[0]; bf[2*pr][1]   = r[1];
                bf[2*pr+1][0] = r[2]; bf[2*pr+1][1] = r[3];
            }
#pragma unroll
            for (int mf = 0; mf < 4; mf++)
#pragma unroll
                for (int nf = 0; nf < 4; nf++)
                    MMA_F16(acc[mf][nf], a[mf], bf[nf]);
        }
        __syncthreads();
    }

    // ---- epilogue: bias + GELU straight from registers ----
    const float* bp = bias + (size_t)e * NT;
#pragma unroll
    for (int mf = 0; mf < 4; mf++) {
#pragma unroll
        for (int nf = 0; nf < 4; nf++) {
            int nn = n0 + wn * 32 + nf * 8 + tig * 2;
            float b0v = __ldg(bp + nn), b1v = __ldg(bp + nn + 1);
#pragma unroll
            for (int half = 0; half < 2; half++) {
                int mrel = wm * 64 + mf * 16 + gid + half * 8;
                if (mrel >= mrem) continue;
                size_t grow = (size_t)(rs + m0 + mrel);
                float v0 = acc[mf][nf][half * 2 + 0] + b0v;
                float v1 = acc[mf][nf][half * 2 + 1] + b1v;
                if (PHASE == 1) {
                    __half2 o = __floats2half2_rn(gelu_tanh(v0), gelu_tanh(v1));
                    *(__half2*)(g_Hh + grow * FF + nn) = o;
                } else {
                    float2 o; o.x = v0; o.y = v1;
                    *(float2*)(g_Y + grow * DD + nn) = o;
                }
            }
        }
    }
}

// ---------------- combine ----------------------------------------------------
__global__ void combine_kernel(float* __restrict__ out) {
    int idx = blockIdx.x * blockDim.x + threadIdx.x;
    if (idx >= TOK * (DD / 4)) return;
    int t  = idx / (DD / 4);
    int n4 = idx % (DD / 4);
    int   r0 = g_rowIdx[2 * t],     r1 = g_rowIdx[2 * t + 1];
    float w0 = g_w[2 * t],          w1 = g_w[2 * t + 1];
    float4 y0 = ((const float4*)(g_Y + (size_t)r0 * DD))[n4];
    float4 y1 = ((const float4*)(g_Y + (size_t)r1 * DD))[n4];
    float4 o;
    o.x = w0 * y0.x + w1 * y1.x;
    o.y = w0 * y0.y + w1 * y1.y;
    o.z = w0 * y0.z + w1 * y1.z;
    o.w = w0 * y0.w + w1 * y1.w;
    ((float4*)out)[idx] = o;
}

// ---------------- launch ------------------------------------------------------
extern "C" void kernel_launch(void* const* d_in, const int* in_sizes, int n_in,
                              void* d_out, int out_size) {
    const float* x  = (const float*)d_in[0];
    const float* gw = (const float*)d_in[1];
    const float* w1 = (const float*)d_in[2];
    const float* b1 = (const float*)d_in[3];
    const float* w2 = (const float*)d_in[4];
    const float* b2 = (const float*)d_in[5];
    float* out = (float*)d_out;

    // one-time host-side resources (no device memory involved)
    static cudaStream_t s2 = nullptr;
    static cudaEvent_t evFork = nullptr, evW1 = nullptr, evW2 = nullptr;
    if (s2 == nullptr) {
        cudaStreamCreateWithFlags(&s2, cudaStreamNonBlocking);
        cudaEventCreateWithFlags(&evFork, cudaEventDisableTiming);
        cudaEventCreateWithFlags(&evW1,   cudaEventDisableTiming);
        cudaEventCreateWithFlags(&evW2,   cudaEventDisableTiming);
    }

    cudaFuncSetAttribute(moe_gemm<1>, cudaFuncAttributeMaxDynamicSharedMemorySize, SMEM_GEMM);
    cudaFuncSetAttribute(moe_gemm<2>, cudaFuncAttributeMaxDynamicSharedMemorySize, SMEM_GEMM);

    // fork: weight conversions run on s2 in parallel with routing chain
    cudaEventRecord(evFork, 0);
    cudaStreamWaitEvent(s2, evFork, 0);
    wtrans_kernel<1><<<dim3(FF / 32, DD / 32, EE), dim3(32, 8), 0, s2>>>(w1);
    cudaEventRecord(evW1, s2);
    wtrans_kernel<2><<<dim3(DD / 32, FF / 32, EE), dim3(32, 8), 0, s2>>>(w2);
    cudaEventRecord(evW2, s2);

    // main chain
    reset_kernel<<<1, 32>>>();
    router_kernel<<<TOK / 8, 256>>>(x, gw);   // also writes g_Xh
    prefix_kernel<<<1, 1>>>();
    scatter_kernel<<<RR / 256, 256>>>();

    cudaStreamWaitEvent(0, evW1, 0);          // W1 ready before gemm1
    moe_gemm<1><<<dim3(FF / 128, RR / 128, EE), 256, SMEM_GEMM>>>(b1);
    cudaStreamWaitEvent(0, evW2, 0);          // W2 ready before gemm2
    moe_gemm<2><<<dim3(DD / 128, RR / 128, EE), 256, SMEM_GEMM>>>(b2);

    combine_kernel<<<(TOK * (DD / 4) + 255) / 256, 256>>>(out);
}